// round 4
// baseline (speedup 1.0000x reference)
#include <cuda_runtime.h>
#include <cstdint>

#define MD 2048
#define ND 8192
#define KD 30522
#define TK 32
#define SPC 0.001

#define HID_OFF   62509056LL   // 2048*30522
#define SCAL_OFF  79286272LL   // + 2048*8192

// ---- device scratch (static globals; no allocations) ----
__device__ float  g_H[(size_t)MD * ND];   // encoder pre-activation
__device__ float  g_inv[ND];              // 1/row-norm of W_dec
__device__ int    g_ti[MD * TK];
__device__ float  g_tv[MD * TK];
__device__ double g_sse, g_sab;
__device__ int    g_act;

__global__ void k_init() { g_sse = 0.0; g_sab = 0.0; g_act = 0; }

// ================= encode GEMM: H = X @ W_enc + b_enc =================
// 128x128 tile, BK=8, 256 threads, 8x8 per thread, double-buffered smem,
// chunked accumulation (flush every 8 tiles = 64 K-terms) for accuracy.
__global__ __launch_bounds__(256, 1) void k_enc(const float* __restrict__ X,
                                                const float* __restrict__ W,
                                                const float* __restrict__ B) {
    __shared__ float As[2][8][132];
    __shared__ float Bs[2][8][128];
    const int tid = threadIdx.x;
    const int m0 = blockIdx.y * 128, n0 = blockIdx.x * 128;
    const int arow = tid >> 1, ak = (tid & 1) * 4;   // A: 128 rows x 8 k
    const int bk = tid >> 5, bn = (tid & 31) * 4;    // B: 8 k x 128 n
    const int row0 = (tid >> 4) * 8, col0 = (tid & 15) * 8;
    const int KT = (KD + 7) / 8;                     // 3816 (= 8*477)

    float2 a0, a1; float4 bv;
    float ch[8][8], tt[8][8];
#pragma unroll
    for (int i = 0; i < 8; i++)
#pragma unroll
        for (int j = 0; j < 8; j++) { ch[i][j] = 0.f; tt[i][j] = 0.f; }

    auto loadT = [&](int t) {
        int gk = t * 8 + ak;
        const float* xp = X + (size_t)(m0 + arow) * KD + gk;
        a0 = (gk     < KD) ? *(const float2*)xp       : make_float2(0.f, 0.f);
        a1 = (gk + 2 < KD) ? *(const float2*)(xp + 2) : make_float2(0.f, 0.f);
        int gbk = t * 8 + bk;
        bv = (gbk < KD) ? *(const float4*)(W + (size_t)gbk * ND + n0 + bn)
                        : make_float4(0.f, 0.f, 0.f, 0.f);
    };
    auto storeT = [&](int b) {
        As[b][ak    ][arow] = a0.x; As[b][ak + 1][arow] = a0.y;
        As[b][ak + 2][arow] = a1.x; As[b][ak + 3][arow] = a1.y;
        *(float4*)&Bs[b][bk][bn] = bv;
    };

    loadT(0); storeT(0); __syncthreads();
    int buf = 0;
    for (int t = 0; t < KT; t++) {
        if (t + 1 < KT) loadT(t + 1);
#pragma unroll
        for (int k = 0; k < 8; k++) {
            float4 av0 = *(const float4*)&As[buf][k][row0];
            float4 av1 = *(const float4*)&As[buf][k][row0 + 4];
            float4 bv0 = *(const float4*)&Bs[buf][k][col0];
            float4 bv1 = *(const float4*)&Bs[buf][k][col0 + 4];
            float a[8] = {av0.x, av0.y, av0.z, av0.w, av1.x, av1.y, av1.z, av1.w};
            float b[8] = {bv0.x, bv0.y, bv0.z, bv0.w, bv1.x, bv1.y, bv1.z, bv1.w};
#pragma unroll
            for (int i = 0; i < 8; i++)
#pragma unroll
                for (int j = 0; j < 8; j++) ch[i][j] = fmaf(a[i], b[j], ch[i][j]);
        }
        if ((t & 7) == 7) {
#pragma unroll
            for (int i = 0; i < 8; i++)
#pragma unroll
                for (int j = 0; j < 8; j++) { tt[i][j] += ch[i][j]; ch[i][j] = 0.f; }
        }
        if (t + 1 < KT) storeT(buf ^ 1);
        __syncthreads();
        buf ^= 1;
    }
    float4 bb0 = *(const float4*)(B + n0 + col0);
    float4 bb1 = *(const float4*)(B + n0 + col0 + 4);
#pragma unroll
    for (int i = 0; i < 8; i++) {
        float* hp = g_H + (size_t)(m0 + row0 + i) * ND + n0 + col0;
        float4 r0 = make_float4(tt[i][0] + bb0.x, tt[i][1] + bb0.y,
                                tt[i][2] + bb0.z, tt[i][3] + bb0.w);
        float4 r1 = make_float4(tt[i][4] + bb1.x, tt[i][5] + bb1.y,
                                tt[i][6] + bb1.z, tt[i][7] + bb1.w);
        *(float4*)hp = r0; *(float4*)(hp + 4) = r1;
    }
}

// ================= W_dec row norms =================
__global__ void k_norm(const float* __restrict__ Wd) {
    int r = blockIdx.x, tid = threadIdx.x;
    const float* p = Wd + (size_t)r * KD;
    float s = 0.f;
    for (int c = tid; c < KD; c += 256) { float w = p[c]; s = fmaf(w, w, s); }
    __shared__ float red[256];
    red[tid] = s; __syncthreads();
    for (int o = 128; o; o >>= 1) { if (tid < o) red[tid] += red[tid + o]; __syncthreads(); }
    if (tid == 0) g_inv[r] = 1.0f / fmaxf(sqrtf(red[0]), 1e-12f);
}

// ================= exact top-32 per row + hidden scatter + sparsity stats =================
__global__ __launch_bounds__(256, 1) void k_topk(float* __restrict__ out) {
    __shared__ unsigned sk[ND];
    __shared__ int scnt, sslot;
    __shared__ int seq[256], spre[256];
    __shared__ float sred[256];
    __shared__ int sredi[256];
    const int tid = threadIdx.x, row = blockIdx.x;
    const float* h = g_H + (size_t)row * ND;
    for (int j = tid; j < ND; j += 256) {
        unsigned b = __float_as_uint(h[j]);
        sk[j] = (b & 0x80000000u) ? ~b : (b | 0x80000000u);   // order-preserving key
    }
    __syncthreads();
    // binary search: T = key value of the 32nd largest (max t with count(>=t) >= 32)
    unsigned T = 0u;
    for (int bit = 31; bit >= 0; bit--) {
        unsigned tr = T | (1u << bit);
        if (tid == 0) scnt = 0;
        __syncthreads();
        int c = 0;
        for (int j = tid; j < ND; j += 256) c += (sk[j] >= tr);
        for (int o = 16; o; o >>= 1) c += __shfl_down_sync(0xffffffffu, c, o);
        if ((tid & 31) == 0) atomicAdd(&scnt, c);
        __syncthreads();
        int tot = scnt;
        __syncthreads();
        if (tot >= TK) T = tr;
    }
    if (tid == 0) scnt = 0;
    __syncthreads();
    { int c = 0;
      for (int j = tid; j < ND; j += 256) c += (sk[j] > T);
      for (int o = 16; o; o >>= 1) c += __shfl_down_sync(0xffffffffu, c, o);
      if ((tid & 31) == 0) atomicAdd(&scnt, c); }
    __syncthreads();
    const int meq = TK - scnt;           // #equals to take (lowest indices, jax tie-break)
    int e = 0;
    for (int j = tid * 32; j < tid * 32 + 32; j++) e += (sk[j] == T);
    seq[tid] = e;
    if (tid == 0) sslot = 0;
    __syncthreads();
    if (tid == 0) { int r = 0; for (int i = 0; i < 256; i++) { spre[i] = r; r += seq[i]; } }
    __syncthreads();
    float sab = 0.f; int act = 0;
    int run = spre[tid];
    float* ho = out + HID_OFF + (size_t)row * ND;
    for (int j = tid * 32; j < tid * 32 + 32; j++) {
        unsigned k = sk[j];
        bool sel = false;
        if (k > T) sel = true;
        else if (k == T) { sel = (run < meq); run++; }
        unsigned vb = (k & 0x80000000u) ? (k ^ 0x80000000u) : ~k;
        float v = __uint_as_float(vb);
        ho[j] = sel ? v : 0.f;
        if (sel) {
            int s = atomicAdd(&sslot, 1);
            g_ti[row * TK + s] = j; g_tv[row * TK + s] = v;
            sab += fabsf(v);
            act += (fabsf(v) > 1e-6f) ? 1 : 0;
        }
    }
    sred[tid] = sab; sredi[tid] = act; __syncthreads();
    for (int o = 128; o; o >>= 1) {
        if (tid < o) { sred[tid] += sred[tid + o]; sredi[tid] += sredi[tid + o]; }
        __syncthreads();
    }
    if (tid == 0) { atomicAdd(&g_sab, (double)sred[0]); atomicAdd(&g_act, sredi[0]); }
}

// ================= decode: recon = hidden @ (Wd/||row||) + b_dec, + SSE =================
__global__ __launch_bounds__(256, 1) void k_dec(const float* __restrict__ X,
                                                const float* __restrict__ Wd,
                                                const float* __restrict__ Bd,
                                                float* __restrict__ out) {
    __shared__ float sv[TK];
    __shared__ size_t so[TK];
    __shared__ float fr[256];
    const int tid = threadIdx.x, row = blockIdx.x;
    if (tid < TK) {
        int id = g_ti[row * TK + tid];
        sv[tid] = g_tv[row * TK + tid] * g_inv[id];
        so[tid] = (size_t)id * KD;
    }
    __syncthreads();
    const float* xr = X + (size_t)row * KD;
    float* rr = out + (size_t)row * KD;
    float sse = 0.f;
    for (int c = tid * 2; c < KD; c += 512) {     // float2: 8B-aligned for odd rows too
        float2 acc = *(const float2*)(Bd + c);
#pragma unroll
        for (int t = 0; t < TK; t++) {
            float2 w = *(const float2*)(Wd + so[t] + c);
            acc.x = fmaf(sv[t], w.x, acc.x);
            acc.y = fmaf(sv[t], w.y, acc.y);
        }
        float2 xv = *(const float2*)(xr + c);
        float dx = acc.x - xv.x, dy = acc.y - xv.y;
        sse = fmaf(dx, dx, sse); sse = fmaf(dy, dy, sse);
        *(float2*)(rr + c) = acc;
    }
    fr[tid] = sse; __syncthreads();
    for (int o = 128; o; o >>= 1) { if (tid < o) fr[tid] += fr[tid + o]; __syncthreads(); }
    if (tid == 0) atomicAdd(&g_sse, (double)fr[0]);
}

__global__ void k_fin(float* out) {
    double rec = g_sse / ((double)MD * KD);
    double sp  = SPC * (g_sab / ((double)MD * ND));
    out[SCAL_OFF + 0] = (float)(rec + sp);
    out[SCAL_OFF + 1] = (float)rec;
    out[SCAL_OFF + 2] = (float)sp;
    out[SCAL_OFF + 3] = (float)g_act / (float)MD;
}

extern "C" void kernel_launch(void* const* d_in, const int* in_sizes, int n_in,
                              void* d_out, int out_size) {
    const float* x  = (const float*)d_in[0];
    const float* We = (const float*)d_in[1];
    const float* be = (const float*)d_in[2];
    const float* Wd = (const float*)d_in[3];
    const float* bd = (const float*)d_in[4];
    float* out = (float*)d_out;

    k_init<<<1, 1>>>();
    dim3 g1(ND / 128, MD / 128);          // 64 x 16
    k_enc<<<g1, 256>>>(x, We, be);
    k_norm<<<ND, 256>>>(Wd);
    k_topk<<<MD, 256>>>(out);
    k_dec<<<MD, 256>>>(x, Wd, bd, out);
    k_fin<<<1, 1>>>(out);
}